// round 12
// baseline (speedup 1.0000x reference)
#include <cuda_runtime.h>
#include <cuda_fp16.h>
#include <cstdint>

#define S_LEN 2048
#define BATCH 2
#define EMB 2048
#define NH 32
#define NKV 8
#define HD 64
#define WIN 128
#define MSEQ 4096   // B*S rows

#define NXE (MSEQ * EMB)       // 8388608
#define NQE (2048 * 2048)      // 4194304
#define NKE (512 * 2048)       // 1048576

// ---------------- scratch (static device globals; no allocation allowed) ----
__device__ __align__(256) __half g_Qa[MSEQ * NH * HD];    // fp16 Q (post-rope)
__device__ __align__(256) __half g_Ka[MSEQ * NKV * HD];   // fp16 K (post-rope)
__device__ __align__(256) __half g_Va[MSEQ * NKV * HD];   // fp16 V

__device__ __align__(256) __half g_xh[NXE];
__device__ __align__(256) __half g_Wqh[NQE];
__device__ __align__(256) __half g_Wkh[NKE];
__device__ __align__(256) __half g_Wvh[NKE];
__device__ __align__(256) __half g_Woh[NQE];
__device__ __align__(256) __half g_ch[MSEQ * 2048];

// ---------------- helpers ---------------------------------------------------
__device__ __forceinline__ uint32_t smem_u32(const void* p) {
    uint32_t a;
    asm("{ .reg .u64 t; cvta.to.shared.u64 t, %1; cvt.u32.u64 %0, t; }"
        : "=r"(a) : "l"(p));
    return a;
}

#define CP16(dst, src) \
    asm volatile("cp.async.cg.shared.global [%0], [%1], 16;" \
                 :: "r"(dst), "l"(src) : "memory")
#define CP_COMMIT() asm volatile("cp.async.commit_group;" ::: "memory")
#define CP_WAIT0()  asm volatile("cp.async.wait_group 0;" ::: "memory")
#define CP_WAIT2()  asm volatile("cp.async.wait_group 2;" ::: "memory")

__device__ __forceinline__ void ldsm4(uint32_t* r, uint32_t addr) {
    asm volatile("ldmatrix.sync.aligned.m8n8.x4.shared.b16 {%0,%1,%2,%3}, [%4];"
                 : "=r"(r[0]), "=r"(r[1]), "=r"(r[2]), "=r"(r[3]) : "r"(addr));
}
__device__ __forceinline__ void ldsm4t(uint32_t* r, uint32_t addr) {
    asm volatile("ldmatrix.sync.aligned.m8n8.x4.trans.shared.b16 {%0,%1,%2,%3}, [%4];"
                 : "=r"(r[0]), "=r"(r[1]), "=r"(r[2]), "=r"(r[3]) : "r"(addr));
}

__device__ __forceinline__ void mma16816(float* d, const uint32_t* a,
                                         uint32_t b0, uint32_t b1) {
    asm volatile(
        "mma.sync.aligned.m16n8k16.row.col.f32.f16.f16.f32 "
        "{%0,%1,%2,%3}, {%4,%5,%6,%7}, {%8,%9}, {%0,%1,%2,%3};"
        : "+f"(d[0]), "+f"(d[1]), "+f"(d[2]), "+f"(d[3])
        : "r"(a[0]), "r"(a[1]), "r"(a[2]), "r"(a[3]), "r"(b0), "r"(b1));
}

__device__ __forceinline__ uint32_t h2u(__half2 h) {
    return *reinterpret_cast<uint32_t*>(&h);
}

// ---------------- fp32 -> fp16 convert, 16 elems/thread (MLP=4) -------------
__global__ void cvt5(const float* __restrict__ x,  const float* __restrict__ wq,
                     const float* __restrict__ wk, const float* __restrict__ wv,
                     const float* __restrict__ wo,
                     __half* __restrict__ xh, __half* __restrict__ wqh,
                     __half* __restrict__ wkh, __half* __restrict__ wvh,
                     __half* __restrict__ woh)
{
    long i = (long)(blockIdx.x * blockDim.x + threadIdx.x) * 16;
    const float* s; __half* d; long off;
    if (i < NXE)                                { s = x;  d = xh;  off = i; }
    else if ((off = i - NXE) < NQE)             { s = wq; d = wqh; }
    else if ((off = i - NXE - NQE) < NKE)       { s = wk; d = wkh; }
    else if ((off = i - NXE - NQE - NKE) < NKE) { s = wv; d = wvh; }
    else {
        off = i - NXE - NQE - 2L * NKE;
        if (off >= NQE) return;
        s = wo; d = woh;
    }
    float4 v0 = *(const float4*)(s + off);
    float4 v1 = *(const float4*)(s + off + 4);
    float4 v2 = *(const float4*)(s + off + 8);
    float4 v3 = *(const float4*)(s + off + 12);
    uint4 u0 = make_uint4(h2u(__floats2half2_rn(v0.x, v0.y)),
                          h2u(__floats2half2_rn(v0.z, v0.w)),
                          h2u(__floats2half2_rn(v1.x, v1.y)),
                          h2u(__floats2half2_rn(v1.z, v1.w)));
    uint4 u1 = make_uint4(h2u(__floats2half2_rn(v2.x, v2.y)),
                          h2u(__floats2half2_rn(v2.z, v2.w)),
                          h2u(__floats2half2_rn(v3.x, v3.y)),
                          h2u(__floats2half2_rn(v3.z, v3.w)));
    *(uint4*)(d + off) = u0;
    *(uint4*)(d + off + 8) = u1;
}

// ============ tensor-core GEMM core: acc += A[128,K] * B[128,K]^T ===========
// 128x128 CTA tile, 4 warps of 64x64 each (2m x 2n), BK=32, 4-stage cp.async.
#define RSTRIDE 80
#define PLANE_B (128 * RSTRIDE)     // 10240 B
#define STAGE_B (2 * PLANE_B)       // 20480 B (A + B)
#define NSTAGE 4
#define GEMM_SMEM (NSTAGE * STAGE_B)  // 81920 B

__device__ __forceinline__ void gemm_core(const __half* __restrict__ A,
                                          const __half* __restrict__ B,
                                          int K, int m0, int n0, char* sm,
                                          float (&acc)[4][8][4])
{
    const uint32_t sb = smem_u32(sm);
    const int tid = threadIdx.x;
    const int wid = tid >> 5;
    const int lane = tid & 31;
    const int warp_m = wid & 1;          // 0..1 -> 64-row slice
    const int warp_n = wid >> 1;         // 0..1 -> 64-col slice

#pragma unroll
    for (int a = 0; a < 4; a++)
#pragma unroll
        for (int b = 0; b < 8; b++)
#pragma unroll
            for (int c = 0; c < 4; c++) acc[a][b][c] = 0.f;

    // stage one BK=32 chunk: 2 planes x 128 rows x 4 x16B groups, 128 threads
    auto stage = [&](int s, int k0) {
        uint32_t dbase = sb + s * STAGE_B;
#pragma unroll
        for (int it = 0; it < 4; it++) {
            int l = tid + it * 128;        // 0..511
            int row = l >> 2;              // 0..127
            int grp = l & 3;               // 16B group
            CP16(dbase + row * RSTRIDE + grp * 16,
                 A + (size_t)(m0 + row) * K + k0 + grp * 8);
            CP16(dbase + PLANE_B + row * RSTRIDE + grp * 16,
                 B + (size_t)(n0 + row) * K + k0 + grp * 8);
        }
    };

    const uint32_t loff =
        ((lane & 7) + ((lane >> 3) & 1) * 8) * RSTRIDE + (lane >> 4) * 16;

    auto compute = [&](int s) {
        uint32_t base = sb + s * STAGE_B;
        uint32_t aA = base + (warp_m * 64) * RSTRIDE + loff;
        uint32_t aB = base + PLANE_B + (warp_n * 64) * RSTRIDE + loff;
#pragma unroll
        for (int ks = 0; ks < 2; ks++) {
            uint32_t ck = ks * 32;
            uint32_t ah[4][4], bb[4][4];
#pragma unroll
            for (int g = 0; g < 4; g++) {
                ldsm4(ah[g], aA + g * 16 * RSTRIDE + ck);
                ldsm4(bb[g], aB + g * 16 * RSTRIDE + ck);
            }
#pragma unroll
            for (int mt = 0; mt < 4; mt++)
#pragma unroll
                for (int nt = 0; nt < 8; nt++)
                    mma16816(acc[mt][nt], ah[mt],
                             bb[nt >> 1][nt & 1], bb[nt >> 1][2 + (nt & 1)]);
        }
    };

    const int nch = K >> 5;       // 64 chunks for K=2048
    stage(0, 0);  CP_COMMIT();
    stage(1, 32); CP_COMMIT();
    stage(2, 64); CP_COMMIT();

    for (int ci = 0; ci < nch; ci++) {
        CP_WAIT2();
        __syncthreads();
        int pf = ci + 3;
        if (pf < nch) stage(pf & 3, pf << 5);
        CP_COMMIT();
        compute(ci & 3);
    }
    __syncthreads();
}

// fp32 epilogue (final output projection)
__device__ __forceinline__ void epi_plain_f(float (&acc)[4][8][4],
                                            const float* __restrict__ bias,
                                            float* __restrict__ C, int N,
                                            int m0, int n0)
{
    const int tid = threadIdx.x;
    const int wid = tid >> 5;
    const int lane = tid & 31;
    const int warp_m = wid & 1;
    const int warp_n = wid >> 1;
#pragma unroll
    for (int mt = 0; mt < 4; mt++) {
        int row = m0 + warp_m * 64 + mt * 16 + (lane >> 2);
#pragma unroll
        for (int nt = 0; nt < 8; nt++) {
            int col = n0 + warp_n * 64 + nt * 8 + (lane & 3) * 2;
            float2 bv = *(const float2*)&bias[col];
            *(float2*)&C[(size_t)row * N + col] =
                make_float2(acc[mt][nt][0] + bv.x, acc[mt][nt][1] + bv.y);
            *(float2*)&C[(size_t)(row + 8) * N + col] =
                make_float2(acc[mt][nt][2] + bv.x, acc[mt][nt][3] + bv.y);
        }
    }
}

// fp16 epilogue (V projection)
__device__ __forceinline__ void epi_plain_h(float (&acc)[4][8][4],
                                            const float* __restrict__ bias,
                                            __half* __restrict__ C, int N,
                                            int m0, int n0)
{
    const int tid = threadIdx.x;
    const int wid = tid >> 5;
    const int lane = tid & 31;
    const int warp_m = wid & 1;
    const int warp_n = wid >> 1;
#pragma unroll
    for (int mt = 0; mt < 4; mt++) {
        int row = m0 + warp_m * 64 + mt * 16 + (lane >> 2);
#pragma unroll
        for (int nt = 0; nt < 8; nt++) {
            int col = n0 + warp_n * 64 + nt * 8 + (lane & 3) * 2;
            float2 bv = *(const float2*)&bias[col];
            *(__half2*)&C[(size_t)row * N + col] =
                __floats2half2_rn(acc[mt][nt][0] + bv.x, acc[mt][nt][1] + bv.y);
            *(__half2*)&C[(size_t)(row + 8) * N + col] =
                __floats2half2_rn(acc[mt][nt][2] + bv.x, acc[mt][nt][3] + bv.y);
        }
    }
}

// fp16 rope epilogue (Q, K): + bias, YaRN rope in fp32, store fp16
__device__ __forceinline__ void epi_rope_h(float (&acc)[4][8][4],
                                           const float* __restrict__ bias,
                                           __half* __restrict__ C, int N,
                                           int m0, int n0,
                                           const int* __restrict__ pos)
{
    const int tid = threadIdx.x;
    const int wid = tid >> 5;
    const int lane = tid & 31;
    const int warp_m = wid & 1;
    const int warp_n = wid >> 1;

    int rbase = m0 + warp_m * 64 + (lane >> 2);
    float posr[8];
#pragma unroll
    for (int q = 0; q < 8; q++) posr[q] = (float)pos[rbase + q * 8];

    const float conc = 1.1386294361119891f;
#pragma unroll
    for (int nt = 0; nt < 4; nt++) {
        int i0 = nt * 8 + (lane & 3) * 2;
        float fr0 = expf(-(float)i0 * 0.2878231366242557f);
        float fr1 = expf(-(float)(i0 + 1) * 0.2878231366242557f);
        float wl0 = 6.283185307179586f / fr0;
        float wl1 = 6.283185307179586f / fr1;
        float t0 = fminf(fmaxf((wl0 - 32.0f) * (1.0f / 992.0f), 0.f), 1.f);
        float t1 = fminf(fmaxf((wl1 - 32.0f) * (1.0f / 992.0f), 0.f), 1.f);
        float e0 = fr0 * (1.0f - 0.75f * t0) * conc;
        float e1 = fr1 * (1.0f - 0.75f * t1) * conc;

        int c0 = n0 + warp_n * 64 + i0;
        float2 b1 = *(const float2*)&bias[c0];
        float2 b2 = *(const float2*)&bias[c0 + 32];
#pragma unroll
        for (int mt = 0; mt < 4; mt++)
#pragma unroll
            for (int sub = 0; sub < 2; sub++) {
                int row = m0 + warp_m * 64 + mt * 16 + (lane >> 2) + sub * 8;
                float p = posr[mt * 2 + sub];
                float s0, cs0, s1, cs1;
                sincosf(p * e0, &s0, &cs0);
                sincosf(p * e1, &s1, &cs1);
                float x1a = acc[mt][nt][sub * 2 + 0] + b1.x;
                float x1b = acc[mt][nt][sub * 2 + 1] + b1.y;
                float x2a = acc[mt][nt + 4][sub * 2 + 0] + b2.x;
                float x2b = acc[mt][nt + 4][sub * 2 + 1] + b2.y;
                *(__half2*)&C[(size_t)row * N + c0] =
                    __floats2half2_rn(x1a * cs0 - x2a * s0, x1b * cs1 - x2b * s1);
                *(__half2*)&C[(size_t)row * N + c0 + 32] =
                    __floats2half2_rn(x2a * cs0 + x1a * s0, x2b * cs1 + x1b * s1);
            }
    }
}

// merged Q/K/V projection (+ fused rope on Q,K). grid (24, 32), 128 threads
__global__ __launch_bounds__(128, 2)
void gemm_qkv(const __half* __restrict__ A,
              const __half* __restrict__ Bq, const __half* __restrict__ Bk,
              const __half* __restrict__ Bv,
              const float* __restrict__ bq, const float* __restrict__ bk,
              const float* __restrict__ bv,
              __half* __restrict__ Cq, __half* __restrict__ Ck,
              __half* __restrict__ Cv, const int* __restrict__ pos)
{
    extern __shared__ char sm[];
    const int bx = blockIdx.x;
    const int m0 = blockIdx.y * 128;
    const __half* B; const float* bias; __half* C; int N, n0; bool rope = true;
    if (bx < 16)      { B = Bq; bias = bq; C = Cq; N = 2048; n0 = bx << 7; }
    else if (bx < 20) { B = Bk; bias = bk; C = Ck; N = 512; n0 = (bx - 16) << 7; }
    else              { B = Bv; bias = bv; C = Cv; N = 512; n0 = (bx - 20) << 7; rope = false; }

    float acc[4][8][4];
    gemm_core(A, B, EMB, m0, n0, sm, acc);
    if (rope) epi_rope_h(acc, bias, C, N, m0, n0, pos);
    else      epi_plain_h(acc, bias, C, N, m0, n0);
}

// output projection. grid (16, 32), 128 threads
__global__ __launch_bounds__(128, 2)
void gemm_o(const __half* __restrict__ A, const __half* __restrict__ B,
            const float* __restrict__ bias, float* __restrict__ C)
{
    extern __shared__ char sm[];
    const int m0 = blockIdx.y * 128;
    const int n0 = blockIdx.x * 128;
    float acc[4][8][4];
    gemm_core(A, B, EMB, m0, n0, sm, acc);
    epi_plain_f(acc, bias, C, EMB, m0, n0);
}

// ============== tensor-core sliding-window flash attention ==================
#define ASTRIDE 144

__global__ __launch_bounds__(128)
void attn_tc(const __half* __restrict__ Qh, const __half* __restrict__ Kh,
             const __half* __restrict__ Vh, const float* __restrict__ sinks,
             __half* __restrict__ ctx)
{
    __shared__ __align__(16) char sQ[64 * ASTRIDE];
    __shared__ __align__(16) char sK[2][64 * ASTRIDE];
    __shared__ __align__(16) char sV[2][64 * ASTRIDE];

    const int b = blockIdx.z;
    const int h = blockIdx.y;
    const int q0 = blockIdx.x * 64;
    const int kvh = h >> 2;
    const int tid = threadIdx.x;
    const int lane = tid & 31;
    const int wid = tid >> 5;
    const uint32_t bQ = smem_u32(sQ);
    const uint32_t bK = smem_u32(sK);
    const uint32_t bV = smem_u32(sV);

#pragma unroll
    for (int it = 0; it < 4; it++) {
        int l = tid + it * 128;
        int row = l >> 3, grp = l & 7;
        CP16(bQ + row * ASTRIDE + grp * 16,
             Qh + (size_t)(b * S_LEN + q0 + row) * 2048 + h * 64 + grp * 8);
    }

    auto loadKV = [&](int buf, int kts) {
#pragma unroll
        for (int it = 0; it < 4; it++) {
            int l = tid + it * 128;
            int row = l >> 3, grp = l & 7;
            size_t g = (size_t)(b * S_LEN + kts + row) * 512 + kvh * 64 + grp * 8;
            CP16(bK + buf * 64 * ASTRIDE + row * ASTRIDE + grp * 16, Kh + g);
            CP16(bV + buf * 64 * ASTRIDE + row * ASTRIDE + grp * 16, Vh + g);
        }
    };

    const int kt_begin = (q0 >= WIN) ? (q0 - WIN) : 0;
    loadKV(0, kt_begin);
    CP_COMMIT();
    CP_WAIT0();
    __syncthreads();

    const uint32_t loff =
        ((lane & 7) + ((lane >> 3) & 1) * 8) * ASTRIDE + (lane >> 4) * 16;

    uint32_t aq[4][4];
    {
        uint32_t qb = bQ + (wid * 16) * ASTRIDE + loff;
#pragma unroll
        for (int ks = 0; ks < 4; ks++) ldsm4(aq[ks], qb + ks * 32);
    }

    const int i_lo = q0 + wid * 16 + (lane >> 2);
    const int i_hi = i_lo + 8;
    float m_lo = -1e4f, m_hi = -1e4f, l_lo = 0.f, l_hi = 0.f;
    float acc_o[8][4];
#pragma unroll
    for (int nt = 0; nt < 8; nt++)
#pragma unroll
        for (int c = 0; c < 4; c++) acc_o[nt][c] = 0.f;

    int buf = 0;
    for (int kts = kt_begin; kts <= q0; kts += 64) {
        if (kts + 64 <= q0) { loadKV(buf ^ 1, kts + 64); CP_COMMIT(); }

        float s[8][4];
#pragma unroll
        for (int nt = 0; nt < 8; nt++)
#pragma unroll
            for (int c = 0; c < 4; c++) s[nt][c] = 0.f;
        uint32_t kb = bK + buf * 64 * ASTRIDE + loff;
#pragma unroll
        for (int ks = 0; ks < 4; ks++) {
            uint32_t bb[4][4];
#pragma unroll
            for (int g = 0; g < 4; g++)
                ldsm4(bb[g], kb + g * 16 * ASTRIDE + ks * 32);
#pragma unroll
            for (int nt = 0; nt < 8; nt++)
                mma16816(s[nt], aq[ks],
                         bb[nt >> 1][nt & 1], bb[nt >> 1][2 + (nt & 1)]);
        }

        float rmax_lo = -3e4f, rmax_hi = -3e4f;
#pragma unroll
        for (int nt = 0; nt < 8; nt++) {
            int j0 = kts + nt * 8 + 2 * (lane & 3);
            int j1 = j0 + 1;
            s[nt][0] = (j0 <= i_lo && j0 > i_lo - WIN) ? s[nt][0] * 0.125f : -3e4f;
            s[nt][1] = (j1 <= i_lo && j1 > i_lo - WIN) ? s[nt][1] * 0.125f : -3e4f;
            s[nt][2] = (j0 <= i_hi && j0 > i_hi - WIN) ? s[nt][2] * 0.125f : -3e4f;
            s[nt][3] = (j1 <= i_hi && j1 > i_hi - WIN) ? s[nt][3] * 0.125f : -3e4f;
            rmax_lo = fmaxf(rmax_lo, fmaxf(s[nt][0], s[nt][1]));
            rmax_hi = fmaxf(rmax_hi, fmaxf(s[nt][2], s[nt][3]));
        }
        rmax_lo = fmaxf(rmax_lo, __shfl_xor_sync(0xffffffffu, rmax_lo, 1));
        rmax_lo = fmaxf(rmax_lo, __shfl_xor_sync(0xffffffffu, rmax_lo, 2));
        rmax_hi = fmaxf(rmax_hi, __shfl_xor_sync(0xffffffffu, rmax_hi, 1));
        rmax_hi = fmaxf(rmax_hi, __shfl_xor_sync(0xffffffffu, rmax_hi, 2));

        float mn_lo = fmaxf(m_lo, rmax_lo);
        float mn_hi = fmaxf(m_hi, rmax_hi);
        float c_lo = __expf(m_lo - mn_lo);
        float c_hi = __expf(m_hi - mn_hi);
        m_lo = mn_lo; m_hi = mn_hi;
        l_lo *= c_lo; l_hi *= c_hi;
#pragma unroll
        for (int nt = 0; nt < 8; nt++) {
            acc_o[nt][0] *= c_lo; acc_o[nt][1] *= c_lo;
            acc_o[nt][2] *= c_hi; acc_o[nt][3] *= c_hi;
        }

        uint32_t ap[4][4];
#pragma unroll
        for (int nt = 0; nt < 8; nt++) {
            float p0 = __expf(s[nt][0] - m_lo);
            float p1 = __expf(s[nt][1] - m_lo);
            float p2 = __expf(s[nt][2] - m_hi);
            float p3 = __expf(s[nt][3] - m_hi);
            l_lo += p0 + p1;
            l_hi += p2 + p3;
            int kt = nt >> 1;
            uint32_t u01 = h2u(__floats2half2_rn(p0, p1));
            uint32_t u23 = h2u(__floats2half2_rn(p2, p3));
            if ((nt & 1) == 0) { ap[kt][0] = u01; ap[kt][1] = u23; }
            else               { ap[kt][2] = u01; ap[kt][3] = u23; }
        }

        uint32_t vb0 = bV + buf * 64 * ASTRIDE + loff;
#pragma unroll
        for (int kt = 0; kt < 4; kt++) {
#pragma unroll
            for (int nbi = 0; nbi < 4; nbi++) {
                uint32_t vb[4];
                ldsm4t(vb, vb0 + kt * 16 * ASTRIDE + nbi * 32);
                mma16816(acc_o[nbi * 2],     ap[kt], vb[0], vb[1]);
                mma16816(acc_o[nbi * 2 + 1], ap[kt], vb[2], vb[3]);
            }
        }

        if (kts + 64 <= q0) CP_WAIT0();
        __syncthreads();
        buf ^= 1;
    }

    l_lo += __shfl_xor_sync(0xffffffffu, l_lo, 1);
    l_lo += __shfl_xor_sync(0xffffffffu, l_lo, 2);
    l_hi += __shfl_xor_sync(0xffffffffu, l_hi, 1);
    l_hi += __shfl_xor_sync(0xffffffffu, l_hi, 2);

    float snk = sinks[h];
    float mf_lo = fmaxf(m_lo, snk);
    float mf_hi = fmaxf(m_hi, snk);
    float e_lo = __expf(m_lo - mf_lo);
    float e_hi = __expf(m_hi - mf_hi);
    float f_lo = e_lo / (l_lo * e_lo + __expf(snk - mf_lo));
    float f_hi = e_hi / (l_hi * e_hi + __expf(snk - mf_hi));

    size_t base_lo = (size_t)(b * S_LEN + i_lo) * 2048 + h * 64;
    size_t base_hi = (size_t)(b * S_LEN + i_hi) * 2048 + h * 64;
#pragma unroll
    for (int nt = 0; nt < 8; nt++) {
        int col = nt * 8 + 2 * (lane & 3);
        *(__half2*)&ctx[base_lo + col] =
            __floats2half2_rn(acc_o[nt][0] * f_lo, acc_o[nt][1] * f_lo);
        *(__half2*)&ctx[base_hi + col] =
            __floats2half2_rn(acc_o[nt][2] * f_hi, acc_o[nt][3] * f_hi);
    }
}

// ---------------- launch -----------------------------------------------------
extern "C" void kernel_launch(void* const* d_in, const int* in_sizes, int n_in,
                              void* d_out, int out_size)
{
    const float* x     = (const float*)d_in[0];
    const float* Wq    = (const float*)d_in[1];
    const float* bq    = (const float*)d_in[2];
    const float* Wk    = (const float*)d_in[3];
    const float* bk    = (const float*)d_in[4];
    const float* Wv    = (const float*)d_in[5];
    const float* bv    = (const float*)d_in[6];
    const float* Wo    = (const float*)d_in[7];
    const float* bo    = (const float*)d_in[8];
    const float* sinks = (const float*)d_in[9];
    const int*   pos   = (const int*)d_in[10];
    float* out = (float*)d_out;

    __half *gQ, *gK, *gV, *xh, *qh, *kh, *vh, *oh, *ch;
    cudaGetSymbolAddress((void**)&gQ, g_Qa);
    cudaGetSymbolAddress((void**)&gK, g_Ka);
    cudaGetSymbolAddress((void**)&gV, g_Va);
    cudaGetSymbolAddress((void**)&xh, g_xh);
    cudaGetSymbolAddress((void**)&qh, g_Wqh);
    cudaGetSymbolAddress((void**)&kh, g_Wkh);
    cudaGetSymbolAddress((void**)&vh, g_Wvh);
    cudaGetSymbolAddress((void**)&oh, g_Woh);
    cudaGetSymbolAddress((void**)&ch, g_ch);

    cudaFuncSetAttribute(gemm_qkv, cudaFuncAttributeMaxDynamicSharedMemorySize,
                         GEMM_SMEM);
    cudaFuncSetAttribute(gemm_o, cudaFuncAttributeMaxDynamicSharedMemorySize,
                         GEMM_SMEM);

    // fp16 conversion of x and all weights, one launch
    long total16 = (NXE + 2L * NQE + 2L * NKE) / 16;
    cvt5<<<(int)((total16 + 255) / 256), 256>>>(x, Wq, Wk, Wv, Wo,
                                                xh, qh, kh, vh, oh);

    // Q/K/V projections + fused YaRN rope (Q,K), fp16 outputs
    gemm_qkv<<<dim3(24, 32), 128, GEMM_SMEM>>>(xh, qh, kh, vh, bq, bk, bv,
                                               gQ, gK, gV, pos);

    // tensor-core windowed attention with sink -> ctx fp16
    attn_tc<<<dim3(S_LEN / 64, NH, BATCH), 128>>>(gQ, gK, gV, sinks, ch);

    // output projection
    gemm_o<<<dim3(16, 32), 128, GEMM_SMEM>>>(ch, oh, bo, out);
}

// round 13
// speedup vs baseline: 1.1069x; 1.1069x over previous
#include <cuda_runtime.h>
#include <cuda_fp16.h>
#include <cstdint>

#define S_LEN 2048
#define BATCH 2
#define EMB 2048
#define NH 32
#define NKV 8
#define HD 64
#define WIN 128
#define MSEQ 4096   // B*S rows

#define NXE (MSEQ * EMB)       // 8388608
#define NQE (2048 * 2048)      // 4194304
#define NKE (512 * 2048)       // 1048576

// ---------------- scratch (static device globals; no allocation allowed) ----
__device__ __align__(256) __half g_Qa[MSEQ * NH * HD];    // fp16 Q (post-rope)
__device__ __align__(256) __half g_Ka[MSEQ * NKV * HD];   // fp16 K (post-rope)
__device__ __align__(256) __half g_Va[MSEQ * NKV * HD];   // fp16 V

__device__ __align__(256) __half g_xh[NXE];
__device__ __align__(256) __half g_Wqh[NQE];
__device__ __align__(256) __half g_Wkh[NKE];
__device__ __align__(256) __half g_Wvh[NKE];
__device__ __align__(256) __half g_Woh[NQE];
__device__ __align__(256) __half g_ch[MSEQ * 2048];

// ---------------- helpers ---------------------------------------------------
__device__ __forceinline__ uint32_t smem_u32(const void* p) {
    uint32_t a;
    asm("{ .reg .u64 t; cvta.to.shared.u64 t, %1; cvt.u32.u64 %0, t; }"
        : "=r"(a) : "l"(p));
    return a;
}

#define CP16(dst, src) \
    asm volatile("cp.async.cg.shared.global [%0], [%1], 16;" \
                 :: "r"(dst), "l"(src) : "memory")
#define CP_COMMIT() asm volatile("cp.async.commit_group;" ::: "memory")
#define CP_WAIT0()  asm volatile("cp.async.wait_group 0;" ::: "memory")
#define CP_WAIT1()  asm volatile("cp.async.wait_group 1;" ::: "memory")

__device__ __forceinline__ void ldsm4(uint32_t* r, uint32_t addr) {
    asm volatile("ldmatrix.sync.aligned.m8n8.x4.shared.b16 {%0,%1,%2,%3}, [%4];"
                 : "=r"(r[0]), "=r"(r[1]), "=r"(r[2]), "=r"(r[3]) : "r"(addr));
}
__device__ __forceinline__ void ldsm4t(uint32_t* r, uint32_t addr) {
    asm volatile("ldmatrix.sync.aligned.m8n8.x4.trans.shared.b16 {%0,%1,%2,%3}, [%4];"
                 : "=r"(r[0]), "=r"(r[1]), "=r"(r[2]), "=r"(r[3]) : "r"(addr));
}

__device__ __forceinline__ void mma16816(float* d, const uint32_t* a,
                                         uint32_t b0, uint32_t b1) {
    asm volatile(
        "mma.sync.aligned.m16n8k16.row.col.f32.f16.f16.f32 "
        "{%0,%1,%2,%3}, {%4,%5,%6,%7}, {%8,%9}, {%0,%1,%2,%3};"
        : "+f"(d[0]), "+f"(d[1]), "+f"(d[2]), "+f"(d[3])
        : "r"(a[0]), "r"(a[1]), "r"(a[2]), "r"(a[3]), "r"(b0), "r"(b1));
}

// fp16-accumulate MMA (rate probe)
__device__ __forceinline__ void mma16816h(uint32_t* d, const uint32_t* a,
                                          uint32_t b0, uint32_t b1) {
    asm volatile(
        "mma.sync.aligned.m16n8k16.row.col.f16.f16.f16.f16 "
        "{%0,%1}, {%2,%3,%4,%5}, {%6,%7}, {%0,%1};"
        : "+r"(d[0]), "+r"(d[1])
        : "r"(a[0]), "r"(a[1]), "r"(a[2]), "r"(a[3]), "r"(b0), "r"(b1));
}
__device__ __forceinline__ void mma16816h_z(uint32_t* d, const uint32_t* a,
                                            uint32_t b0, uint32_t b1) {
    asm volatile(
        "mma.sync.aligned.m16n8k16.row.col.f16.f16.f16.f16 "
        "{%0,%1}, {%2,%3,%4,%5}, {%6,%7}, {%8,%9};"
        : "=r"(d[0]), "=r"(d[1])
        : "r"(a[0]), "r"(a[1]), "r"(a[2]), "r"(a[3]), "r"(b0), "r"(b1),
          "r"(0u), "r"(0u));
}

__device__ __forceinline__ uint32_t h2u(__half2 h) {
    return *reinterpret_cast<uint32_t*>(&h);
}
__device__ __forceinline__ __half2 u2h(uint32_t u) {
    return *reinterpret_cast<__half2*>(&u);
}

// ---------------- fp32 -> fp16 convert, 16 elems/thread (MLP=4) -------------
__global__ void cvt5(const float* __restrict__ x,  const float* __restrict__ wq,
                     const float* __restrict__ wk, const float* __restrict__ wv,
                     const float* __restrict__ wo,
                     __half* __restrict__ xh, __half* __restrict__ wqh,
                     __half* __restrict__ wkh, __half* __restrict__ wvh,
                     __half* __restrict__ woh)
{
    long i = (long)(blockIdx.x * blockDim.x + threadIdx.x) * 16;
    const float* s; __half* d; long off;
    if (i < NXE)                                { s = x;  d = xh;  off = i; }
    else if ((off = i - NXE) < NQE)             { s = wq; d = wqh; }
    else if ((off = i - NXE - NQE) < NKE)       { s = wk; d = wkh; }
    else if ((off = i - NXE - NQE - NKE) < NKE) { s = wv; d = wvh; }
    else {
        off = i - NXE - NQE - 2L * NKE;
        if (off >= NQE) return;
        s = wo; d = woh;
    }
    float4 v0 = *(const float4*)(s + off);
    float4 v1 = *(const float4*)(s + off + 4);
    float4 v2 = *(const float4*)(s + off + 8);
    float4 v3 = *(const float4*)(s + off + 12);
    uint4 u0 = make_uint4(h2u(__floats2half2_rn(v0.x, v0.y)),
                          h2u(__floats2half2_rn(v0.z, v0.w)),
                          h2u(__floats2half2_rn(v1.x, v1.y)),
                          h2u(__floats2half2_rn(v1.z, v1.w)));
    uint4 u1 = make_uint4(h2u(__floats2half2_rn(v2.x, v2.y)),
                          h2u(__floats2half2_rn(v2.z, v2.w)),
                          h2u(__floats2half2_rn(v3.x, v3.y)),
                          h2u(__floats2half2_rn(v3.z, v3.w)));
    *(uint4*)(d + off) = u0;
    *(uint4*)(d + off + 8) = u1;
}

// ===== R10 tensor-core GEMM core (f32 acc): 128x128 CTA, warp 32x64 ========
#define GSTRIDE 144
#define PLANE_B (128 * GSTRIDE)     // 18432 B
#define STAGE_B (2 * PLANE_B)       // A + B
#define GEMM_SMEM (2 * STAGE_B)     // 73728 B

__device__ __forceinline__ void gemm_core(const __half* __restrict__ A,
                                          const __half* __restrict__ B,
                                          int K, int m0, int n0, char* sm,
                                          float (&acc)[2][8][4])
{
    const uint32_t sb = smem_u32(sm);
    const int tid = threadIdx.x;
    const int wid = tid >> 5;
    const int lane = tid & 31;
    const int warp_m = wid & 3;
    const int warp_n = wid >> 2;

#pragma unroll
    for (int a = 0; a < 2; a++)
#pragma unroll
        for (int b = 0; b < 8; b++)
#pragma unroll
            for (int c = 0; c < 4; c++) acc[a][b][c] = 0.f;

    auto stage = [&](int buf, int k0) {
        uint32_t dbase = sb + buf * STAGE_B;
#pragma unroll
        for (int it = 0; it < 4; it++) {
            int l = tid + it * 256;
            int row = l >> 3;
            int grp = l & 7;
            CP16(dbase + row * GSTRIDE + grp * 16,
                 A + (size_t)(m0 + row) * K + k0 + grp * 8);
            CP16(dbase + PLANE_B + row * GSTRIDE + grp * 16,
                 B + (size_t)(n0 + row) * K + k0 + grp * 8);
        }
    };

    const uint32_t loff =
        ((lane & 7) + ((lane >> 3) & 1) * 8) * GSTRIDE + (lane >> 4) * 16;

    auto compute = [&](int buf) {
        uint32_t base = sb + buf * STAGE_B;
        uint32_t aA = base + (warp_m * 32) * GSTRIDE + loff;
        uint32_t aB = base + PLANE_B + (warp_n * 64) * GSTRIDE + loff;
#pragma unroll
        for (int ks = 0; ks < 4; ks++) {
            uint32_t ck = ks * 32;
            uint32_t ah[2][4], bb[4][4];
            ldsm4(ah[0], aA + ck);
            ldsm4(ah[1], aA + 16 * GSTRIDE + ck);
#pragma unroll
            for (int g = 0; g < 4; g++)
                ldsm4(bb[g], aB + g * 16 * GSTRIDE + ck);
#pragma unroll
            for (int mt = 0; mt < 2; mt++)
#pragma unroll
                for (int nt = 0; nt < 8; nt++)
                    mma16816(acc[mt][nt], ah[mt],
                             bb[nt >> 1][nt & 1], bb[nt >> 1][2 + (nt & 1)]);
        }
    };

    stage(0, 0);
    CP_COMMIT();
    const int nch = K >> 6;
    int buf = 0;
    for (int ci = 0; ci < nch; ci++) {
        if (ci + 1 < nch) {
            stage(buf ^ 1, (ci + 1) << 6);
            CP_COMMIT();
            CP_WAIT1();
        } else {
            CP_WAIT0();
        }
        __syncthreads();
        compute(buf);
        __syncthreads();
        buf ^= 1;
    }
}

// fp16 epilogue (V projection)
__device__ __forceinline__ void epi_plain_h(float (&acc)[2][8][4],
                                            const float* __restrict__ bias,
                                            __half* __restrict__ C, int N,
                                            int m0, int n0)
{
    const int tid = threadIdx.x;
    const int wid = tid >> 5;
    const int lane = tid & 31;
    const int warp_m = wid & 3;
    const int warp_n = wid >> 2;
#pragma unroll
    for (int mt = 0; mt < 2; mt++) {
        int row = m0 + warp_m * 32 + mt * 16 + (lane >> 2);
#pragma unroll
        for (int nt = 0; nt < 8; nt++) {
            int col = n0 + warp_n * 64 + nt * 8 + (lane & 3) * 2;
            float2 bv = *(const float2*)&bias[col];
            *(__half2*)&C[(size_t)row * N + col] =
                __floats2half2_rn(acc[mt][nt][0] + bv.x, acc[mt][nt][1] + bv.y);
            *(__half2*)&C[(size_t)(row + 8) * N + col] =
                __floats2half2_rn(acc[mt][nt][2] + bv.x, acc[mt][nt][3] + bv.y);
        }
    }
}

// fp16 rope epilogue (Q, K): + bias, YaRN rope in fp32, store fp16
__device__ __forceinline__ void epi_rope_h(float (&acc)[2][8][4],
                                           const float* __restrict__ bias,
                                           __half* __restrict__ C, int N,
                                           int m0, int n0,
                                           const int* __restrict__ pos)
{
    const int tid = threadIdx.x;
    const int wid = tid >> 5;
    const int lane = tid & 31;
    const int warp_m = wid & 3;
    const int warp_n = wid >> 2;

    int rbase = m0 + warp_m * 32 + (lane >> 2);
    float posr[4];
    posr[0] = (float)pos[rbase];
    posr[1] = (float)pos[rbase + 8];
    posr[2] = (float)pos[rbase + 16];
    posr[3] = (float)pos[rbase + 24];

    const float conc = 1.1386294361119891f;
#pragma unroll
    for (int nt = 0; nt < 4; nt++) {
        int i0 = nt * 8 + (lane & 3) * 2;
        float fr0 = expf(-(float)i0 * 0.2878231366242557f);
        float fr1 = expf(-(float)(i0 + 1) * 0.2878231366242557f);
        float wl0 = 6.283185307179586f / fr0;
        float wl1 = 6.283185307179586f / fr1;
        float t0 = fminf(fmaxf((wl0 - 32.0f) * (1.0f / 992.0f), 0.f), 1.f);
        float t1 = fminf(fmaxf((wl1 - 32.0f) * (1.0f / 992.0f), 0.f), 1.f);
        float e0 = fr0 * (1.0f - 0.75f * t0) * conc;
        float e1 = fr1 * (1.0f - 0.75f * t1) * conc;

        int c0 = n0 + warp_n * 64 + i0;
        float2 b1 = *(const float2*)&bias[c0];
        float2 b2 = *(const float2*)&bias[c0 + 32];
#pragma unroll
        for (int mt = 0; mt < 2; mt++)
#pragma unroll
            for (int sub = 0; sub < 2; sub++) {
                int row = m0 + warp_m * 32 + mt * 16 + (lane >> 2) + sub * 8;
                float p = posr[mt * 2 + sub];
                float s0, cs0, s1, cs1;
                sincosf(p * e0, &s0, &cs0);
                sincosf(p * e1, &s1, &cs1);
                float x1a = acc[mt][nt][sub * 2 + 0] + b1.x;
                float x1b = acc[mt][nt][sub * 2 + 1] + b1.y;
                float x2a = acc[mt][nt + 4][sub * 2 + 0] + b2.x;
                float x2b = acc[mt][nt + 4][sub * 2 + 1] + b2.y;
                *(__half2*)&C[(size_t)row * N + c0] =
                    __floats2half2_rn(x1a * cs0 - x2a * s0, x1b * cs1 - x2b * s1);
                *(__half2*)&C[(size_t)row * N + c0 + 32] =
                    __floats2half2_rn(x2a * cs0 + x1a * s0, x2b * cs1 + x1b * s1);
            }
    }
}

// merged Q/K/V projection (+ fused rope on Q,K). grid (24, 32), 256 threads
__global__ __launch_bounds__(256, 2)
void gemm_qkv(const __half* __restrict__ A,
              const __half* __restrict__ Bq, const __half* __restrict__ Bk,
              const __half* __restrict__ Bv,
              const float* __restrict__ bq, const float* __restrict__ bk,
              const float* __restrict__ bv,
              __half* __restrict__ Cq, __half* __restrict__ Ck,
              __half* __restrict__ Cv, const int* __restrict__ pos)
{
    extern __shared__ char sm[];
    const int bx = blockIdx.x;
    const int m0 = blockIdx.y * 128;
    const __half* B; const float* bias; __half* C; int N, n0; bool rope = true;
    if (bx < 16)      { B = Bq; bias = bq; C = Cq; N = 2048; n0 = bx << 7; }
    else if (bx < 20) { B = Bk; bias = bk; C = Ck; N = 512; n0 = (bx - 16) << 7; }
    else              { B = Bv; bias = bv; C = Cv; N = 512; n0 = (bx - 20) << 7; rope = false; }

    float acc[2][8][4];
    gemm_core(A, B, EMB, m0, n0, sm, acc);
    if (rope) epi_rope_h(acc, bias, C, N, m0, n0, pos);
    else      epi_plain_h(acc, bias, C, N, m0, n0);
}

// ===== output projection, fp16-accumulate probe: CTA 128x64, warp 32x32 ====
#define HPLANE_A (128 * GSTRIDE)            // 18432
#define HPLANE_Bp (64 * GSTRIDE)            // 9216
#define HSTAGE (HPLANE_A + HPLANE_Bp)       // 27648
#define GEMM_SMEM_H (2 * HSTAGE)            // 55296

__global__ __launch_bounds__(256, 2)
void gemm_o_h(const __half* __restrict__ A, const __half* __restrict__ B,
              const float* __restrict__ bias, float* __restrict__ C)
{
    extern __shared__ char sm[];
    const uint32_t sb = smem_u32(sm);
    const int tid = threadIdx.x;
    const int wid = tid >> 5;
    const int lane = tid & 31;
    const int warp_m = wid & 3;          // 4 x 32 rows
    const int warp_n = wid >> 2;         // 2 x 32 cols
    const int m0 = blockIdx.y * 128;
    const int n0 = blockIdx.x * 64;
    const int K = EMB, N = EMB;

    float acc[2][4][4];
#pragma unroll
    for (int a = 0; a < 2; a++)
#pragma unroll
        for (int b = 0; b < 4; b++)
#pragma unroll
            for (int c = 0; c < 4; c++) acc[a][b][c] = 0.f;

    auto stage = [&](int buf, int k0) {
        uint32_t dbase = sb + buf * HSTAGE;
#pragma unroll
        for (int it = 0; it < 4; it++) {              // A: 128 rows
            int l = tid + it * 256;
            int row = l >> 3;
            int grp = l & 7;
            CP16(dbase + row * GSTRIDE + grp * 16,
                 A + (size_t)(m0 + row) * K + k0 + grp * 8);
        }
#pragma unroll
        for (int it = 0; it < 2; it++) {              // B: 64 rows
            int l = tid + it * 256;
            int row = l >> 3;
            int grp = l & 7;
            CP16(dbase + HPLANE_A + row * GSTRIDE + grp * 16,
                 B + (size_t)(n0 + row) * K + k0 + grp * 8);
        }
    };

    const uint32_t loff =
        ((lane & 7) + ((lane >> 3) & 1) * 8) * GSTRIDE + (lane >> 4) * 16;

    auto compute = [&](int buf) {
        uint32_t base = sb + buf * HSTAGE;
        uint32_t aA = base + (warp_m * 32) * GSTRIDE + loff;
        uint32_t aB = base + HPLANE_A + (warp_n * 32) * GSTRIDE + loff;
        uint32_t hd[2][4][2];
#pragma unroll
        for (int ks = 0; ks < 4; ks++) {
            uint32_t ck = ks * 32;
            uint32_t ah[2][4], bb[2][4];
            ldsm4(ah[0], aA + ck);
            ldsm4(ah[1], aA + 16 * GSTRIDE + ck);
            ldsm4(bb[0], aB + ck);
            ldsm4(bb[1], aB + 16 * GSTRIDE + ck);
#pragma unroll
            for (int mt = 0; mt < 2; mt++)
#pragma unroll
                for (int nt = 0; nt < 4; nt++) {
                    uint32_t b0 = bb[nt >> 1][nt & 1];
                    uint32_t b1 = bb[nt >> 1][2 + (nt & 1)];
                    if (ks == 0) mma16816h_z(hd[mt][nt], ah[mt], b0, b1);
                    else         mma16816h(hd[mt][nt], ah[mt], b0, b1);
                }
        }
        // flush f16 chunk-accumulators into f32
#pragma unroll
        for (int mt = 0; mt < 2; mt++)
#pragma unroll
            for (int nt = 0; nt < 4; nt++) {
                float2 f0 = __half22float2(u2h(hd[mt][nt][0]));
                float2 f1 = __half22float2(u2h(hd[mt][nt][1]));
                acc[mt][nt][0] += f0.x;
                acc[mt][nt][1] += f0.y;
                acc[mt][nt][2] += f1.x;
                acc[mt][nt][3] += f1.y;
            }
    };

    stage(0, 0);
    CP_COMMIT();
    const int nch = K >> 6;
    int buf = 0;
    for (int ci = 0; ci < nch; ci++) {
        if (ci + 1 < nch) {
            stage(buf ^ 1, (ci + 1) << 6);
            CP_COMMIT();
            CP_WAIT1();
        } else {
            CP_WAIT0();
        }
        __syncthreads();
        compute(buf);
        __syncthreads();
        buf ^= 1;
    }

    // epilogue: + bias, fp32 out
#pragma unroll
    for (int mt = 0; mt < 2; mt++) {
        int row = m0 + warp_m * 32 + mt * 16 + (lane >> 2);
#pragma unroll
        for (int nt = 0; nt < 4; nt++) {
            int col = n0 + warp_n * 32 + nt * 8 + (lane & 3) * 2;
            float2 bv = *(const float2*)&bias[col];
            *(float2*)&C[(size_t)row * N + col] =
                make_float2(acc[mt][nt][0] + bv.x, acc[mt][nt][1] + bv.y);
            *(float2*)&C[(size_t)(row + 8) * N + col] =
                make_float2(acc[mt][nt][2] + bv.x, acc[mt][nt][3] + bv.y);
        }
    }
}

// ============== tensor-core sliding-window flash attention ==================
#define ASTRIDE 144

__global__ __launch_bounds__(128)
void attn_tc(const __half* __restrict__ Qh, const __half* __restrict__ Kh,
             const __half* __restrict__ Vh, const float* __restrict__ sinks,
             __half* __restrict__ ctx)
{
    __shared__ __align__(16) char sQ[64 * ASTRIDE];
    __shared__ __align__(16) char sK[2][64 * ASTRIDE];
    __shared__ __align__(16) char sV[2][64 * ASTRIDE];

    const int b = blockIdx.z;
    const int h = blockIdx.y;
    const int q0 = blockIdx.x * 64;
    const int kvh = h >> 2;
    const int tid = threadIdx.x;
    const int lane = tid & 31;
    const int wid = tid >> 5;
    const uint32_t bQ = smem_u32(sQ);
    const uint32_t bK = smem_u32(sK);
    const uint32_t bV = smem_u32(sV);

#pragma unroll
    for (int it = 0; it < 4; it++) {
        int l = tid + it * 128;
        int row = l >> 3, grp = l & 7;
        CP16(bQ + row * ASTRIDE + grp * 16,
             Qh + (size_t)(b * S_LEN + q0 + row) * 2048 + h * 64 + grp * 8);
    }

    auto loadKV = [&](int buf, int kts) {
#pragma unroll
        for (int it = 0; it < 4; it++) {
            int l = tid + it * 128;
            int row = l >> 3, grp = l & 7;
            size_t g = (size_t)(b * S_LEN + kts + row) * 512 + kvh * 64 + grp * 8;
            CP16(bK + buf * 64 * ASTRIDE + row * ASTRIDE + grp * 16, Kh + g);
            CP16(bV + buf * 64 * ASTRIDE + row * ASTRIDE + grp * 16, Vh + g);
        }
    };

    const int kt_begin = (q0 >= WIN) ? (q0 - WIN) : 0;
    loadKV(0, kt_begin);
    CP_COMMIT();
    CP_WAIT0();
    __syncthreads();

    const uint32_t loff =
        ((lane & 7) + ((lane >> 3) & 1) * 8) * ASTRIDE + (lane >> 4) * 16;

    uint32_t aq[4][4];
    {
        uint32_t qb = bQ + (wid * 16) * ASTRIDE + loff;
#pragma unroll
        for (int ks = 0; ks < 4; ks++) ldsm4(aq[ks], qb + ks * 32);
    }

    const int i_lo = q0 + wid * 16 + (lane >> 2);
    const int i_hi = i_lo + 8;
    float m_lo = -1e4f, m_hi = -1e4f, l_lo = 0.f, l_hi = 0.f;
    float acc_o[8][4];
#pragma unroll
    for (int nt = 0; nt < 8; nt++)
#pragma unroll
        for (int c = 0; c < 4; c++) acc_o[nt][c] = 0.f;

    int buf = 0;
    for (int kts = kt_begin; kts <= q0; kts += 64) {
        if (kts + 64 <= q0) { loadKV(buf ^ 1, kts + 64); CP_COMMIT(); }

        float s[8][4];
#pragma unroll
        for (int nt = 0; nt < 8; nt++)
#pragma unroll
            for (int c = 0; c < 4; c++) s[nt][c] = 0.f;
        uint32_t kb = bK + buf * 64 * ASTRIDE + loff;
#pragma unroll
        for (int ks = 0; ks < 4; ks++) {
            uint32_t bb[4][4];
#pragma unroll
            for (int g = 0; g < 4; g++)
                ldsm4(bb[g], kb + g * 16 * ASTRIDE + ks * 32);
#pragma unroll
            for (int nt = 0; nt < 8; nt++)
                mma16816(s[nt], aq[ks],
                         bb[nt >> 1][nt & 1], bb[nt >> 1][2 + (nt & 1)]);
        }

        float rmax_lo = -3e4f, rmax_hi = -3e4f;
#pragma unroll
        for (int nt = 0; nt < 8; nt++) {
            int j0 = kts + nt * 8 + 2 * (lane & 3);
            int j1 = j0 + 1;
            s[nt][0] = (j0 <= i_lo && j0 > i_lo - WIN) ? s[nt][0] * 0.125f : -3e4f;
            s[nt][1] = (j1 <= i_lo && j1 > i_lo - WIN) ? s[nt][1] * 0.125f : -3e4f;
            s[nt][2] = (j0 <= i_hi && j0 > i_hi - WIN) ? s[nt][2] * 0.125f : -3e4f;
            s[nt][3] = (j1 <= i_hi && j1 > i_hi - WIN) ? s[nt][3] * 0.125f : -3e4f;
            rmax_lo = fmaxf(rmax_lo, fmaxf(s[nt][0], s[nt][1]));
            rmax_hi = fmaxf(rmax_hi, fmaxf(s[nt][2], s[nt][3]));
        }
        rmax_lo = fmaxf(rmax_lo, __shfl_xor_sync(0xffffffffu, rmax_lo, 1));
        rmax_lo = fmaxf(rmax_lo, __shfl_xor_sync(0xffffffffu, rmax_lo, 2));
        rmax_hi = fmaxf(rmax_hi, __shfl_xor_sync(0xffffffffu, rmax_hi, 1));
        rmax_hi = fmaxf(rmax_hi, __shfl_xor_sync(0xffffffffu, rmax_hi, 2));

        float mn_lo = fmaxf(m_lo, rmax_lo);
        float mn_hi = fmaxf(m_hi, rmax_hi);
        float c_lo = __expf(m_lo - mn_lo);
        float c_hi = __expf(m_hi - mn_hi);
        m_lo = mn_lo; m_hi = mn_hi;
        l_lo *= c_lo; l_hi *= c_hi;
#pragma unroll
        for (int nt = 0; nt < 8; nt++) {
            acc_o[nt][0] *= c_lo; acc_o[nt][1] *= c_lo;
            acc_o[nt][2] *= c_hi; acc_o[nt][3] *= c_hi;
        }

        uint32_t ap[4][4];
#pragma unroll
        for (int nt = 0; nt < 8; nt++) {
            float p0 = __expf(s[nt][0] - m_lo);
            float p1 = __expf(s[nt][1] - m_lo);
            float p2 = __expf(s[nt][2] - m_hi);
            float p3 = __expf(s[nt][3] - m_hi);
            l_lo += p0 + p1;
            l_hi += p2 + p3;
            int kt = nt >> 1;
            uint32_t u01 = h2u(__floats2half2_rn(p0, p1));
            uint32_t u23 = h2u(__floats2half2_rn(p2, p3));
            if ((nt & 1) == 0) { ap[kt][0] = u01; ap[kt][1] = u23; }
            else               { ap[kt][2] = u01; ap[kt][3] = u23; }
        }

        uint32_t vb0 = bV + buf * 64 * ASTRIDE + loff;
#pragma unroll
        for (int kt = 0; kt < 4; kt++) {
#pragma unroll
            for (int nbi = 0; nbi < 4; nbi++) {
                uint32_t vb[4];
                ldsm4t(vb, vb0 + kt * 16 * ASTRIDE + nbi * 32);
                mma16816(acc_o[nbi * 2],     ap[kt], vb[0], vb[1]);
                mma16816(acc_o[nbi * 2 + 1], ap[kt], vb[2], vb[3]);
            }
        }

        if (kts + 64 <= q0) CP_WAIT0();
        __syncthreads();
        buf ^= 1;
    }

    l_lo += __shfl_xor_sync(0xffffffffu, l_lo, 1);
    l_lo += __shfl_xor_sync(0xffffffffu, l_lo, 2);
    l_hi += __shfl_xor_sync(0xffffffffu, l_hi, 1);
    l_hi += __shfl_xor_sync(0xffffffffu, l_hi, 2);

    float snk = sinks[h];
    float mf_lo = fmaxf(m_lo, snk);
    float mf_hi = fmaxf(m_hi, snk);
    float e_lo = __expf(m_lo - mf_lo);
    float e_hi = __expf(m_hi - mf_hi);
    float f_lo = e_lo / (l_lo * e_lo + __expf(snk - mf_lo));
    float f_hi = e_hi / (l_hi * e_hi + __expf(snk - mf_hi));

    size_t base_lo = (size_t)(b * S_LEN + i_lo) * 2048 + h * 64;
    size_t base_hi = (size_t)(b * S_LEN + i_hi) * 2048 + h * 64;
#pragma unroll
    for (int nt = 0; nt < 8; nt++) {
        int col = nt * 8 + 2 * (lane & 3);
        *(__half2*)&ctx[base_lo + col] =
            __floats2half2_rn(acc_o[nt][0] * f_lo, acc_o[nt][1] * f_lo);
        *(__half2*)&ctx[base_hi + col] =
            __floats2half2_rn(acc_o[nt][2] * f_hi, acc_o[nt][3] * f_hi);
    }
}

// ---------------- launch -----------------------------------------------------
extern "C" void kernel_launch(void* const* d_in, const int* in_sizes, int n_in,
                              void* d_out, int out_size)
{
    const float* x     = (const float*)d_in[0];
    const float* Wq    = (const float*)d_in[1];
    const float* bq    = (const float*)d_in[2];
    const float* Wk    = (const float*)d_in[3];
    const float* bk    = (const float*)d_in[4];
    const float* Wv    = (const float*)d_in[5];
    const float* bv    = (const float*)d_in[6];
    const float* Wo    = (const float*)d_in[7];
    const float* bo    = (const float*)d_in[8];
    const float* sinks = (const float*)d_in[9];
    const int*   pos   = (const int*)d_in[10];
    float* out = (float*)d_out;

    __half *gQ, *gK, *gV, *xh, *qh, *kh, *vh, *oh, *ch;
    cudaGetSymbolAddress((void**)&gQ, g_Qa);
    cudaGetSymbolAddress((void**)&gK, g_Ka);
    cudaGetSymbolAddress((void**)&gV, g_Va);
    cudaGetSymbolAddress((void**)&xh, g_xh);
    cudaGetSymbolAddress((void**)&qh, g_Wqh);
    cudaGetSymbolAddress((void**)&kh, g_Wkh);
    cudaGetSymbolAddress((void**)&vh, g_Wvh);
    cudaGetSymbolAddress((void**)&oh, g_Woh);
    cudaGetSymbolAddress((void**)&ch, g_ch);

    cudaFuncSetAttribute(gemm_qkv, cudaFuncAttributeMaxDynamicSharedMemorySize,
                         GEMM_SMEM);
    cudaFuncSetAttribute(gemm_o_h, cudaFuncAttributeMaxDynamicSharedMemorySize,
                         GEMM_SMEM_H);

    // fp16 conversion of x and all weights, one launch
    long total16 = (NXE + 2L * NQE + 2L * NKE) / 16;
    cvt5<<<(int)((total16 + 255) / 256), 256>>>(x, Wq, Wk, Wv, Wo,
                                                xh, qh, kh, vh, oh);

    // Q/K/V projections + fused YaRN rope (Q,K), fp16 outputs (R10 core)
    gemm_qkv<<<dim3(24, 32), 256, GEMM_SMEM>>>(xh, qh, kh, vh, bq, bk, bv,
                                               gQ, gK, gV, pos);

    // tensor-core windowed attention with sink -> ctx fp16
    attn_tc<<<dim3(S_LEN / 64, NH, BATCH), 128>>>(gQ, gK, gV, sinks, ch);

    // output projection — fp16-accumulate rate probe
    gemm_o_h<<<dim3(32, 32), 256, GEMM_SMEM_H>>>(ch, oh, bo, out);
}

// round 14
// speedup vs baseline: 1.1566x; 1.0448x over previous
#include <cuda_runtime.h>
#include <cuda_fp16.h>
#include <cstdint>

#define S_LEN 2048
#define BATCH 2
#define EMB 2048
#define NH 32
#define NKV 8
#define HD 64
#define WIN 128
#define MSEQ 4096   // B*S rows

#define NXE (MSEQ * EMB)       // 8388608
#define NQE (2048 * 2048)      // 4194304
#define NKE (512 * 2048)       // 1048576

// ---------------- scratch (static device globals; no allocation allowed) ----
__device__ __align__(256) __half g_Qa[MSEQ * NH * HD];    // fp16 Q (post-rope)
__device__ __align__(256) __half g_Ka[MSEQ * NKV * HD];   // fp16 K (post-rope)
__device__ __align__(256) __half g_Va[MSEQ * NKV * HD];   // fp16 V

__device__ __align__(256) __half g_xh[NXE];
__device__ __align__(256) __half g_Wqh[NQE];
__device__ __align__(256) __half g_Wkh[NKE];
__device__ __align__(256) __half g_Wvh[NKE];
__device__ __align__(256) __half g_Woh[NQE];
__device__ __align__(256) __half g_ch[MSEQ * 2048];

// ---------------- helpers ---------------------------------------------------
__device__ __forceinline__ uint32_t smem_u32(const void* p) {
    uint32_t a;
    asm("{ .reg .u64 t; cvta.to.shared.u64 t, %1; cvt.u32.u64 %0, t; }"
        : "=r"(a) : "l"(p));
    return a;
}

#define CP16(dst, src) \
    asm volatile("cp.async.cg.shared.global [%0], [%1], 16;" \
                 :: "r"(dst), "l"(src) : "memory")
#define CP_COMMIT() asm volatile("cp.async.commit_group;" ::: "memory")
#define CP_WAIT0()  asm volatile("cp.async.wait_group 0;" ::: "memory")
#define CP_WAIT1()  asm volatile("cp.async.wait_group 1;" ::: "memory")

__device__ __forceinline__ void ldsm4(uint32_t* r, uint32_t addr) {
    asm volatile("ldmatrix.sync.aligned.m8n8.x4.shared.b16 {%0,%1,%2,%3}, [%4];"
                 : "=r"(r[0]), "=r"(r[1]), "=r"(r[2]), "=r"(r[3]) : "r"(addr));
}
__device__ __forceinline__ void ldsm4t(uint32_t* r, uint32_t addr) {
    asm volatile("ldmatrix.sync.aligned.m8n8.x4.trans.shared.b16 {%0,%1,%2,%3}, [%4];"
                 : "=r"(r[0]), "=r"(r[1]), "=r"(r[2]), "=r"(r[3]) : "r"(addr));
}

__device__ __forceinline__ void mma16816(float* d, const uint32_t* a,
                                         uint32_t b0, uint32_t b1) {
    asm volatile(
        "mma.sync.aligned.m16n8k16.row.col.f32.f16.f16.f32 "
        "{%0,%1,%2,%3}, {%4,%5,%6,%7}, {%8,%9}, {%0,%1,%2,%3};"
        : "+f"(d[0]), "+f"(d[1]), "+f"(d[2]), "+f"(d[3])
        : "r"(a[0]), "r"(a[1]), "r"(a[2]), "r"(a[3]), "r"(b0), "r"(b1));
}

__device__ __forceinline__ uint32_t h2u(__half2 h) {
    return *reinterpret_cast<uint32_t*>(&h);
}

// ---------------- fp32 -> fp16 convert, 16 elems/thread (MLP=4) -------------
__global__ void cvt5(const float* __restrict__ x,  const float* __restrict__ wq,
                     const float* __restrict__ wk, const float* __restrict__ wv,
                     const float* __restrict__ wo,
                     __half* __restrict__ xh, __half* __restrict__ wqh,
                     __half* __restrict__ wkh, __half* __restrict__ wvh,
                     __half* __restrict__ woh)
{
    long i = (long)(blockIdx.x * blockDim.x + threadIdx.x) * 16;
    const float* s; __half* d; long off;
    if (i < NXE)                                { s = x;  d = xh;  off = i; }
    else if ((off = i - NXE) < NQE)             { s = wq; d = wqh; }
    else if ((off = i - NXE - NQE) < NKE)       { s = wk; d = wkh; }
    else if ((off = i - NXE - NQE - NKE) < NKE) { s = wv; d = wvh; }
    else {
        off = i - NXE - NQE - 2L * NKE;
        if (off >= NQE) return;
        s = wo; d = woh;
    }
    float4 v0 = *(const float4*)(s + off);
    float4 v1 = *(const float4*)(s + off + 4);
    float4 v2 = *(const float4*)(s + off + 8);
    float4 v3 = *(const float4*)(s + off + 12);
    uint4 u0 = make_uint4(h2u(__floats2half2_rn(v0.x, v0.y)),
                          h2u(__floats2half2_rn(v0.z, v0.w)),
                          h2u(__floats2half2_rn(v1.x, v1.y)),
                          h2u(__floats2half2_rn(v1.z, v1.w)));
    uint4 u1 = make_uint4(h2u(__floats2half2_rn(v2.x, v2.y)),
                          h2u(__floats2half2_rn(v2.z, v2.w)),
                          h2u(__floats2half2_rn(v3.x, v3.y)),
                          h2u(__floats2half2_rn(v3.z, v3.w)));
    *(uint4*)(d + off) = u0;
    *(uint4*)(d + off + 8) = u1;
}

// ===== GEMM core v3: CTA 128x64, 8 warps of 32x32, 3 CTAs/SM ==============
// acc layout: acc[mt(2)][nt(4)][4]; col(nt) = (nt&2 ? 32 : 0) + warp_n*16
//             + (nt&1)*8 + (lane&3)*2   (interleaved for in-thread rope pairs)
#define GSTRIDE 144
#define PLANE_A3 (128 * GSTRIDE)            // 18432
#define STAGE3 (PLANE_A3 + 64 * GSTRIDE)    // 27648
#define GEMM3_SMEM (2 * STAGE3)             // 55296

__device__ __forceinline__ void gemm_core3(const __half* __restrict__ A,
                                           const __half* __restrict__ B,
                                           int K, int m0, int n0, char* sm,
                                           float (&acc)[2][4][4])
{
    const uint32_t sb = smem_u32(sm);
    const int tid = threadIdx.x;
    const int wid = tid >> 5;
    const int lane = tid & 31;
    const int warp_m = wid & 3;          // 4 x 32 rows
    const int warp_n = wid >> 2;         // 2 x (16+16 interleaved) cols

#pragma unroll
    for (int a = 0; a < 2; a++)
#pragma unroll
        for (int b = 0; b < 4; b++)
#pragma unroll
            for (int c = 0; c < 4; c++) acc[a][b][c] = 0.f;

    auto stage = [&](int buf, int k0) {
        uint32_t dbase = sb + buf * STAGE3;
#pragma unroll
        for (int it = 0; it < 4; it++) {              // A: 128 rows
            int l = tid + it * 256;
            int row = l >> 3;
            int grp = l & 7;
            CP16(dbase + row * GSTRIDE + grp * 16,
                 A + (size_t)(m0 + row) * K + k0 + grp * 8);
        }
#pragma unroll
        for (int it = 0; it < 2; it++) {              // B: 64 rows
            int l = tid + it * 256;
            int row = l >> 3;
            int grp = l & 7;
            CP16(dbase + PLANE_A3 + row * GSTRIDE + grp * 16,
                 B + (size_t)(n0 + row) * K + k0 + grp * 8);
        }
    };

    const uint32_t loff =
        ((lane & 7) + ((lane >> 3) & 1) * 8) * GSTRIDE + (lane >> 4) * 16;

    auto compute = [&](int buf) {
        uint32_t base = sb + buf * STAGE3;
        uint32_t aA = base + (warp_m * 32) * GSTRIDE + loff;
        uint32_t aB0 = base + PLANE_A3 + (warp_n * 16) * GSTRIDE + loff;
        uint32_t aB1 = base + PLANE_A3 + (32 + warp_n * 16) * GSTRIDE + loff;
#pragma unroll
        for (int ks = 0; ks < 4; ks++) {
            uint32_t ck = ks * 32;
            uint32_t ah[2][4], bb[2][4];
            ldsm4(ah[0], aA + ck);
            ldsm4(ah[1], aA + 16 * GSTRIDE + ck);
            ldsm4(bb[0], aB0 + ck);
            ldsm4(bb[1], aB1 + ck);
#pragma unroll
            for (int mt = 0; mt < 2; mt++)
#pragma unroll
                for (int nt = 0; nt < 4; nt++)
                    mma16816(acc[mt][nt], ah[mt],
                             bb[nt >> 1][nt & 1], bb[nt >> 1][2 + (nt & 1)]);
        }
    };

    stage(0, 0);
    CP_COMMIT();
    const int nch = K >> 6;
    int buf = 0;
    for (int ci = 0; ci < nch; ci++) {
        if (ci + 1 < nch) {
            stage(buf ^ 1, (ci + 1) << 6);
            CP_COMMIT();
            CP_WAIT1();
        } else {
            CP_WAIT0();
        }
        __syncthreads();
        compute(buf);
        __syncthreads();
        buf ^= 1;
    }
}

__device__ __forceinline__ int col_of(int nt, int warp_n, int lane) {
    return ((nt & 2) ? 32 : 0) + warp_n * 16 + (nt & 1) * 8 + (lane & 3) * 2;
}

// fp32 epilogue (output projection)
__device__ __forceinline__ void epi3_f(float (&acc)[2][4][4],
                                       const float* __restrict__ bias,
                                       float* __restrict__ C, int N,
                                       int m0, int n0)
{
    const int tid = threadIdx.x;
    const int wid = tid >> 5;
    const int lane = tid & 31;
    const int warp_m = wid & 3;
    const int warp_n = wid >> 2;
#pragma unroll
    for (int mt = 0; mt < 2; mt++) {
        int row = m0 + warp_m * 32 + mt * 16 + (lane >> 2);
#pragma unroll
        for (int nt = 0; nt < 4; nt++) {
            int col = n0 + col_of(nt, warp_n, lane);
            float2 bv = *(const float2*)&bias[col];
            *(float2*)&C[(size_t)row * N + col] =
                make_float2(acc[mt][nt][0] + bv.x, acc[mt][nt][1] + bv.y);
            *(float2*)&C[(size_t)(row + 8) * N + col] =
                make_float2(acc[mt][nt][2] + bv.x, acc[mt][nt][3] + bv.y);
        }
    }
}

// fp16 epilogue (V projection)
__device__ __forceinline__ void epi3_h(float (&acc)[2][4][4],
                                       const float* __restrict__ bias,
                                       __half* __restrict__ C, int N,
                                       int m0, int n0)
{
    const int tid = threadIdx.x;
    const int wid = tid >> 5;
    const int lane = tid & 31;
    const int warp_m = wid & 3;
    const int warp_n = wid >> 2;
#pragma unroll
    for (int mt = 0; mt < 2; mt++) {
        int row = m0 + warp_m * 32 + mt * 16 + (lane >> 2);
#pragma unroll
        for (int nt = 0; nt < 4; nt++) {
            int col = n0 + col_of(nt, warp_n, lane);
            float2 bv = *(const float2*)&bias[col];
            *(__half2*)&C[(size_t)row * N + col] =
                __floats2half2_rn(acc[mt][nt][0] + bv.x, acc[mt][nt][1] + bv.y);
            *(__half2*)&C[(size_t)(row + 8) * N + col] =
                __floats2half2_rn(acc[mt][nt][2] + bv.x, acc[mt][nt][3] + bv.y);
        }
    }
}

// fp16 rope epilogue: pairs (nt, nt+2) hold (x1, x2) of the same head
__device__ __forceinline__ void epi3_rope(float (&acc)[2][4][4],
                                          const float* __restrict__ bias,
                                          __half* __restrict__ C, int N,
                                          int m0, int n0,
                                          const int* __restrict__ pos)
{
    const int tid = threadIdx.x;
    const int wid = tid >> 5;
    const int lane = tid & 31;
    const int warp_m = wid & 3;
    const int warp_n = wid >> 2;

    int rbase = m0 + warp_m * 32 + (lane >> 2);
    float posr[4];
    posr[0] = (float)pos[rbase];
    posr[1] = (float)pos[rbase + 8];
    posr[2] = (float)pos[rbase + 16];
    posr[3] = (float)pos[rbase + 24];

    const float conc = 1.1386294361119891f;
#pragma unroll
    for (int nt = 0; nt < 2; nt++) {
        int i0 = warp_n * 16 + nt * 8 + (lane & 3) * 2;   // head-relative 0..31
        float fr0 = expf(-(float)i0 * 0.2878231366242557f);
        float fr1 = expf(-(float)(i0 + 1) * 0.2878231366242557f);
        float wl0 = 6.283185307179586f / fr0;
        float wl1 = 6.283185307179586f / fr1;
        float t0 = fminf(fmaxf((wl0 - 32.0f) * (1.0f / 992.0f), 0.f), 1.f);
        float t1 = fminf(fmaxf((wl1 - 32.0f) * (1.0f / 992.0f), 0.f), 1.f);
        float e0 = fr0 * (1.0f - 0.75f * t0) * conc;
        float e1 = fr1 * (1.0f - 0.75f * t1) * conc;

        int c0 = n0 + i0;
        float2 b1 = *(const float2*)&bias[c0];
        float2 b2 = *(const float2*)&bias[c0 + 32];
#pragma unroll
        for (int mt = 0; mt < 2; mt++)
#pragma unroll
            for (int sub = 0; sub < 2; sub++) {
                int row = m0 + warp_m * 32 + mt * 16 + (lane >> 2) + sub * 8;
                float p = posr[mt * 2 + sub];
                float s0, cs0, s1, cs1;
                sincosf(p * e0, &s0, &cs0);
                sincosf(p * e1, &s1, &cs1);
                float x1a = acc[mt][nt][sub * 2 + 0] + b1.x;
                float x1b = acc[mt][nt][sub * 2 + 1] + b1.y;
                float x2a = acc[mt][nt + 2][sub * 2 + 0] + b2.x;
                float x2b = acc[mt][nt + 2][sub * 2 + 1] + b2.y;
                *(__half2*)&C[(size_t)row * N + c0] =
                    __floats2half2_rn(x1a * cs0 - x2a * s0, x1b * cs1 - x2b * s1);
                *(__half2*)&C[(size_t)row * N + c0 + 32] =
                    __floats2half2_rn(x2a * cs0 + x1a * s0, x2b * cs1 + x1b * s1);
            }
    }
}

// merged Q/K/V projection. grid (48, 32): 32 Q n-tiles + 8 K + 8 V (64 wide)
__global__ __launch_bounds__(256, 3)
void gemm_qkv(const __half* __restrict__ A,
              const __half* __restrict__ Bq, const __half* __restrict__ Bk,
              const __half* __restrict__ Bv,
              const float* __restrict__ bq, const float* __restrict__ bk,
              const float* __restrict__ bv,
              __half* __restrict__ Cq, __half* __restrict__ Ck,
              __half* __restrict__ Cv, const int* __restrict__ pos)
{
    extern __shared__ char sm[];
    const int bx = blockIdx.x;
    const int m0 = blockIdx.y * 128;
    const __half* B; const float* bias; __half* C; int N, n0; bool rope = true;
    if (bx < 32)      { B = Bq; bias = bq; C = Cq; N = 2048; n0 = bx << 6; }
    else if (bx < 40) { B = Bk; bias = bk; C = Ck; N = 512; n0 = (bx - 32) << 6; }
    else              { B = Bv; bias = bv; C = Cv; N = 512; n0 = (bx - 40) << 6; rope = false; }

    float acc[2][4][4];
    gemm_core3(A, B, EMB, m0, n0, sm, acc);
    if (rope) epi3_rope(acc, bias, C, N, m0, n0, pos);
    else      epi3_h(acc, bias, C, N, m0, n0);
}

// output projection. grid (32, 32)
__global__ __launch_bounds__(256, 3)
void gemm_o(const __half* __restrict__ A, const __half* __restrict__ B,
            const float* __restrict__ bias, float* __restrict__ C)
{
    extern __shared__ char sm[];
    const int m0 = blockIdx.y * 128;
    const int n0 = blockIdx.x * 64;
    float acc[2][4][4];
    gemm_core3(A, B, EMB, m0, n0, sm, acc);
    epi3_f(acc, bias, C, EMB, m0, n0);
}

// ============== tensor-core sliding-window flash attention ==================
#define ASTRIDE 144

__global__ __launch_bounds__(128)
void attn_tc(const __half* __restrict__ Qh, const __half* __restrict__ Kh,
             const __half* __restrict__ Vh, const float* __restrict__ sinks,
             __half* __restrict__ ctx)
{
    __shared__ __align__(16) char sQ[64 * ASTRIDE];
    __shared__ __align__(16) char sK[2][64 * ASTRIDE];
    __shared__ __align__(16) char sV[2][64 * ASTRIDE];

    const int b = blockIdx.z;
    const int h = blockIdx.y;
    const int q0 = blockIdx.x * 64;
    const int kvh = h >> 2;
    const int tid = threadIdx.x;
    const int lane = tid & 31;
    const int wid = tid >> 5;
    const uint32_t bQ = smem_u32(sQ);
    const uint32_t bK = smem_u32(sK);
    const uint32_t bV = smem_u32(sV);

#pragma unroll
    for (int it = 0; it < 4; it++) {
        int l = tid + it * 128;
        int row = l >> 3, grp = l & 7;
        CP16(bQ + row * ASTRIDE + grp * 16,
             Qh + (size_t)(b * S_LEN + q0 + row) * 2048 + h * 64 + grp * 8);
    }

    auto loadKV = [&](int buf, int kts) {
#pragma unroll
        for (int it = 0; it < 4; it++) {
            int l = tid + it * 128;
            int row = l >> 3, grp = l & 7;
            size_t g = (size_t)(b * S_LEN + kts + row) * 512 + kvh * 64 + grp * 8;
            CP16(bK + buf * 64 * ASTRIDE + row * ASTRIDE + grp * 16, Kh + g);
            CP16(bV + buf * 64 * ASTRIDE + row * ASTRIDE + grp * 16, Vh + g);
        }
    };

    const int kt_begin = (q0 >= WIN) ? (q0 - WIN) : 0;
    loadKV(0, kt_begin);
    CP_COMMIT();
    CP_WAIT0();
    __syncthreads();

    const uint32_t loff =
        ((lane & 7) + ((lane >> 3) & 1) * 8) * ASTRIDE + (lane >> 4) * 16;

    uint32_t aq[4][4];
    {
        uint32_t qb = bQ + (wid * 16) * ASTRIDE + loff;
#pragma unroll
        for (int ks = 0; ks < 4; ks++) ldsm4(aq[ks], qb + ks * 32);
    }

    const int i_lo = q0 + wid * 16 + (lane >> 2);
    const int i_hi = i_lo + 8;
    float m_lo = -1e4f, m_hi = -1e4f, l_lo = 0.f, l_hi = 0.f;
    float acc_o[8][4];
#pragma unroll
    for (int nt = 0; nt < 8; nt++)
#pragma unroll
        for (int c = 0; c < 4; c++) acc_o[nt][c] = 0.f;

    int buf = 0;
    for (int kts = kt_begin; kts <= q0; kts += 64) {
        if (kts + 64 <= q0) { loadKV(buf ^ 1, kts + 64); CP_COMMIT(); }

        float s[8][4];
#pragma unroll
        for (int nt = 0; nt < 8; nt++)
#pragma unroll
            for (int c = 0; c < 4; c++) s[nt][c] = 0.f;
        uint32_t kb = bK + buf * 64 * ASTRIDE + loff;
#pragma unroll
        for (int ks = 0; ks < 4; ks++) {
            uint32_t bb[4][4];
#pragma unroll
            for (int g = 0; g < 4; g++)
                ldsm4(bb[g], kb + g * 16 * ASTRIDE + ks * 32);
#pragma unroll
            for (int nt = 0; nt < 8; nt++)
                mma16816(s[nt], aq[ks],
                         bb[nt >> 1][nt & 1], bb[nt >> 1][2 + (nt & 1)]);
        }

        float rmax_lo = -3e4f, rmax_hi = -3e4f;
#pragma unroll
        for (int nt = 0; nt < 8; nt++) {
            int j0 = kts + nt * 8 + 2 * (lane & 3);
            int j1 = j0 + 1;
            s[nt][0] = (j0 <= i_lo && j0 > i_lo - WIN) ? s[nt][0] * 0.125f : -3e4f;
            s[nt][1] = (j1 <= i_lo && j1 > i_lo - WIN) ? s[nt][1] * 0.125f : -3e4f;
            s[nt][2] = (j0 <= i_hi && j0 > i_hi - WIN) ? s[nt][2] * 0.125f : -3e4f;
            s[nt][3] = (j1 <= i_hi && j1 > i_hi - WIN) ? s[nt][3] * 0.125f : -3e4f;
            rmax_lo = fmaxf(rmax_lo, fmaxf(s[nt][0], s[nt][1]));
            rmax_hi = fmaxf(rmax_hi, fmaxf(s[nt][2], s[nt][3]));
        }
        rmax_lo = fmaxf(rmax_lo, __shfl_xor_sync(0xffffffffu, rmax_lo, 1));
        rmax_lo = fmaxf(rmax_lo, __shfl_xor_sync(0xffffffffu, rmax_lo, 2));
        rmax_hi = fmaxf(rmax_hi, __shfl_xor_sync(0xffffffffu, rmax_hi, 1));
        rmax_hi = fmaxf(rmax_hi, __shfl_xor_sync(0xffffffffu, rmax_hi, 2));

        float mn_lo = fmaxf(m_lo, rmax_lo);
        float mn_hi = fmaxf(m_hi, rmax_hi);
        float c_lo = __expf(m_lo - mn_lo);
        float c_hi = __expf(m_hi - mn_hi);
        m_lo = mn_lo; m_hi = mn_hi;
        l_lo *= c_lo; l_hi *= c_hi;
#pragma unroll
        for (int nt = 0; nt < 8; nt++) {
            acc_o[nt][0] *= c_lo; acc_o[nt][1] *= c_lo;
            acc_o[nt][2] *= c_hi; acc_o[nt][3] *= c_hi;
        }

        uint32_t ap[4][4];
#pragma unroll
        for (int nt = 0; nt < 8; nt++) {
            float p0 = __expf(s[nt][0] - m_lo);
            float p1 = __expf(s[nt][1] - m_lo);
            float p2 = __expf(s[nt][2] - m_hi);
            float p3 = __expf(s[nt][3] - m_hi);
            l_lo += p0 + p1;
            l_hi += p2 + p3;
            int kt = nt >> 1;
            uint32_t u01 = h2u(__floats2half2_rn(p0, p1));
            uint32_t u23 = h2u(__floats2half2_rn(p2, p3));
            if ((nt & 1) == 0) { ap[kt][0] = u01; ap[kt][1] = u23; }
            else               { ap[kt][2] = u01; ap[kt][3] = u23; }
        }

        uint32_t vb0 = bV + buf * 64 * ASTRIDE + loff;
#pragma unroll
        for (int kt = 0; kt < 4; kt++) {
#pragma unroll
            for (int nbi = 0; nbi < 4; nbi++) {
                uint32_t vb[4];
                ldsm4t(vb, vb0 + kt * 16 * ASTRIDE + nbi * 32);
                mma16816(acc_o[nbi * 2],     ap[kt], vb[0], vb[1]);
                mma16816(acc_o[nbi * 2 + 1], ap[kt], vb[2], vb[3]);
            }
        }

        if (kts + 64 <= q0) CP_WAIT0();
        __syncthreads();
        buf ^= 1;
    }

    l_lo += __shfl_xor_sync(0xffffffffu, l_lo, 1);
    l_lo += __shfl_xor_sync(0xffffffffu, l_lo, 2);
    l_hi += __shfl_xor_sync(0xffffffffu, l_hi, 1);
    l_hi += __shfl_xor_sync(0xffffffffu, l_hi, 2);

    float snk = sinks[h];
    float mf_lo = fmaxf(m_lo, snk);
    float mf_hi = fmaxf(m_hi, snk);
    float e_lo = __expf(m_lo - mf_lo);
    float e_hi = __expf(m_hi - mf_hi);
    float f_lo = e_lo / (l_lo * e_lo + __expf(snk - mf_lo));
    float f_hi = e_hi / (l_hi * e_hi + __expf(snk - mf_hi));

    size_t base_lo = (size_t)(b * S_LEN + i_lo) * 2048 + h * 64;
    size_t base_hi = (size_t)(b * S_LEN + i_hi) * 2048 + h * 64;
#pragma unroll
    for (int nt = 0; nt < 8; nt++) {
        int col = nt * 8 + 2 * (lane & 3);
        *(__half2*)&ctx[base_lo + col] =
            __floats2half2_rn(acc_o[nt][0] * f_lo, acc_o[nt][1] * f_lo);
        *(__half2*)&ctx[base_hi + col] =
            __floats2half2_rn(acc_o[nt][2] * f_hi, acc_o[nt][3] * f_hi);
    }
}

// ---------------- launch -----------------------------------------------------
extern "C" void kernel_launch(void* const* d_in, const int* in_sizes, int n_in,
                              void* d_out, int out_size)
{
    const float* x     = (const float*)d_in[0];
    const float* Wq    = (const float*)d_in[1];
    const float* bq    = (const float*)d_in[2];
    const float* Wk    = (const float*)d_in[3];
    const float* bk    = (const float*)d_in[4];
    const float* Wv    = (const float*)d_in[5];
    const float* bv    = (const float*)d_in[6];
    const float* Wo    = (const float*)d_in[7];
    const float* bo    = (const float*)d_in[8];
    const float* sinks = (const float*)d_in[9];
    const int*   pos   = (const int*)d_in[10];
    float* out = (float*)d_out;

    __half *gQ, *gK, *gV, *xh, *qh, *kh, *vh, *oh, *ch;
    cudaGetSymbolAddress((void**)&gQ, g_Qa);
    cudaGetSymbolAddress((void**)&gK, g_Ka);
    cudaGetSymbolAddress((void**)&gV, g_Va);
    cudaGetSymbolAddress((void**)&xh, g_xh);
    cudaGetSymbolAddress((void**)&qh, g_Wqh);
    cudaGetSymbolAddress((void**)&kh, g_Wkh);
    cudaGetSymbolAddress((void**)&vh, g_Wvh);
    cudaGetSymbolAddress((void**)&oh, g_Woh);
    cudaGetSymbolAddress((void**)&ch, g_ch);

    cudaFuncSetAttribute(gemm_qkv, cudaFuncAttributeMaxDynamicSharedMemorySize,
                         GEMM3_SMEM);
    cudaFuncSetAttribute(gemm_o, cudaFuncAttributeMaxDynamicSharedMemorySize,
                         GEMM3_SMEM);

    // fp16 conversion of x and all weights, one launch
    long total16 = (NXE + 2L * NQE + 2L * NKE) / 16;
    cvt5<<<(int)((total16 + 255) / 256), 256>>>(x, Wq, Wk, Wv, Wo,
                                                xh, qh, kh, vh, oh);

    // Q/K/V projections + fused YaRN rope (Q,K), fp16 outputs
    gemm_qkv<<<dim3(48, 32), 256, GEMM3_SMEM>>>(xh, qh, kh, vh, bq, bk, bv,
                                                gQ, gK, gV, pos);

    // tensor-core windowed attention with sink -> ctx fp16
    attn_tc<<<dim3(S_LEN / 64, NH, BATCH), 128>>>(gQ, gK, gV, sinks, ch);

    // output projection
    gemm_o<<<dim3(32, 32), 256, GEMM3_SMEM>>>(ch, oh, bo, out);
}